// round 15
// baseline (speedup 1.0000x reference)
#include <cuda_runtime.h>
#include <cuda_fp16.h>
#include <math.h>

#define N_NODES 50000
#define N_EDGES 800000
#define C1 256
#define C2 32
#define NEG 0.2f
#define FULLMASK 0xffffffffu
#define MAXDEG 128

// ---------------- scratch ----------------
__device__ __align__(16) __half g_xr1h[(size_t)N_NODES * C1];
__device__ __align__(16) __half g_xr2h[(size_t)N_NODES * C2];
__device__ __align__(16) __half g_xl1h[(size_t)N_NODES * C1];
__device__ __align__(16) __half g_xl2h[(size_t)N_NODES * C2];
__device__ __align__(16) __half g_h1h[(size_t)N_NODES * C1];    // h1 fp16
__device__ __align__(16) __half g_b1l[(size_t)C1 * 128];        // W1l fp16 [n][k]
__device__ __align__(16) __half g_b1r[(size_t)C1 * 128];
__device__ __align__(16) __half g_b2l[(size_t)C2 * 256];
__device__ __align__(16) __half g_b2r[(size_t)C2 * 256];
__device__ __align__(16) int    g_cnt[N_NODES];                 // zero at entry; reset by gat2_final
__device__ __align__(16) int    g_adj[(size_t)N_NODES * MAXDEG];
__device__ int g_is64;

#define BUFH_B1L  0
#define BUFH_B1R  1
#define BUFH_H1H  2
#define BUFH_B2L  3
#define BUFH_B2R  4
#define BUFH_XL1H 5
#define BUFH_XL2H 6
#define BUFH_XR1H 7
#define BUFH_XR2H 8
__device__ __forceinline__ __half* devbufh(int id) {
    switch (id) {
        case BUFH_B1L:  return g_b1l;
        case BUFH_B1R:  return g_b1r;
        case BUFH_H1H:  return g_h1h;
        case BUFH_B2L:  return g_b2l;
        case BUFH_B2R:  return g_b2r;
        case BUFH_XL1H: return g_xl1h;
        case BUFH_XL2H: return g_xl2h;
        case BUFH_XR1H: return g_xr1h;
        default:        return g_xr2h;
    }
}

__device__ __forceinline__ unsigned pack_h2(__half a, __half b) {
    __half2 p = __halves2half2(a, b);
    return *reinterpret_cast<unsigned*>(&p);
}

// ---------------- convall: dtype detect + all 4 weight conversions ----------------
__global__ void convall_kernel(const float* __restrict__ W1l, const float* __restrict__ W1r,
                               const float* __restrict__ W2l, const float* __restrict__ W2r,
                               const void* __restrict__ ei) {
    int idx = blockIdx.x * blockDim.x + threadIdx.x;
    if (idx == 0) {
        const unsigned long long* p = (const unsigned long long*)ei;
        int ok = 1;
        for (int q = 0; q < 64; q++)
            if (p[q] >> 32) { ok = 0; break; }
        g_is64 = ok;
    }
    if (idx < 32768) {               // b1l/b1r: [256][128] from W1{l,r} [128,256]
        int n = idx >> 7, k = idx & 127;
        g_b1l[idx] = __float2half_rn(W1l[(size_t)k * 256 + n]);
        g_b1r[idx] = __float2half_rn(W1r[(size_t)k * 256 + n]);
    } else if (idx < 32768 + 8192) { // b2l/b2r: [32][256] from W2{l,r} [256,32]
        int j = idx - 32768;
        int n = j >> 8, k = j & 255;
        g_b2l[j] = __float2half_rn(W2l[(size_t)k * 32 + n]);
        g_b2r[j] = __float2half_rn(W2r[(size_t)k * 32 + n]);
    }
}

__device__ __forceinline__ int edge_at(const void* __restrict__ ei, int row, int e) {
    if (g_is64) return (int)((const long long*)ei)[(size_t)row * N_EDGES + e];
    return ((const int*)ei)[(size_t)row * N_EDGES + e];
}

// ---------------- direct padded-CSR scatter (g_cnt starts at 0) ----------------
__global__ void scatter_direct_kernel(const void* __restrict__ ei) {
    int e = blockIdx.x * blockDim.x + threadIdx.x;
    if (e < N_EDGES) {
        int src = edge_at(ei, 0, e);
        int dst = edge_at(ei, 1, e);
        src = min(max(src, 0), N_NODES - 1);
        dst = min(max(dst, 0), N_NODES - 1);
        int slot = atomicAdd(&g_cnt[dst], 1);
        if (slot < MAXDEG)
            g_adj[(size_t)dst * MAXDEG + slot] = src;
    }
}

// ---------------- fp16 tensor-core dual GEMM (both outputs fp16) ----------------
__device__ __forceinline__ void mma16816(float* c, const unsigned* a, const unsigned* b) {
    asm volatile(
        "mma.sync.aligned.m16n8k16.row.col.f32.f16.f16.f32 "
        "{%0,%1,%2,%3}, {%4,%5,%6,%7}, {%8,%9}, {%0,%1,%2,%3};"
        : "+f"(c[0]), "+f"(c[1]), "+f"(c[2]), "+f"(c[3])
        : "r"(a[0]), "r"(a[1]), "r"(a[2]), "r"(a[3]), "r"(b[0]), "r"(b[1]));
}
__device__ __forceinline__ void ldsm_x4(unsigned& r0, unsigned& r1, unsigned& r2, unsigned& r3,
                                        unsigned addr) {
    asm volatile("ldmatrix.sync.aligned.m8n8.x4.shared.b16 {%0,%1,%2,%3}, [%4];"
                 : "=r"(r0), "=r"(r1), "=r"(r2), "=r"(r3) : "r"(addr));
}
__device__ __forceinline__ void ldsm_x2(unsigned& r0, unsigned& r1, unsigned addr) {
    asm volatile("ldmatrix.sync.aligned.m8n8.x2.shared.b16 {%0,%1}, [%2];"
                 : "=r"(r0), "=r"(r1) : "r"(addr));
}

template <int BM, int BN, int BK, int WM, int WN, int K, bool CONV_A>
__global__ __launch_bounds__(WM * WN * 32, 2)
void hgemm_dual_kernel(const float* __restrict__ a_f32, int a_id,
                       int b0_id, int b1_id, int c0h_id, int c1h_id,
                       int M, int Nh) {
    constexpr int THREADS = WM * WN * 32;
    constexpr int WTM = BM / WM;
    constexpr int WTN = BN / WN;
    constexpr int MT = WTM / 16;
    constexpr int NT = WTN / 8;
    constexpr int LDS_ = BK + 8;
    constexpr int T = K / BK;
    constexpr int NA = (BM * BK / 8) / THREADS;
    constexpr int NB = (BN * BK / 8) / THREADS;

    __shared__ __half Ah[BM][LDS_];
    __shared__ __half Bhs[BN][LDS_];

    const int colL = blockIdx.y * BN;
    const int hsel = (colL >= Nh) ? 1 : 0;
    const __half* B = devbufh(hsel ? b1_id : b0_id);
    const int col0 = colL - hsel * Nh;

    const int tid = threadIdx.x;
    const int row0 = blockIdx.x * BM;
    const int wid = tid >> 5;
    const int lane = tid & 31;
    const int wm = wid / WN, wn = wid % WN;
    const int g = lane >> 2, tig = lane & 3;

    const unsigned sAh = (unsigned)__cvta_generic_to_shared(&Ah[0][0]);
    const unsigned sBh = (unsigned)__cvta_generic_to_shared(&Bhs[0][0]);

    float acc[MT][NT][4];
    #pragma unroll
    for (int i = 0; i < MT; i++)
        #pragma unroll
        for (int j = 0; j < NT; j++)
            #pragma unroll
            for (int q = 0; q < 4; q++) acc[i][j][q] = 0.f;

    float rfa[NA][8];
    uint4 rha[NA];
    uint4 rhb[NB];

    auto LOAD = [&](int k0) {
        #pragma unroll
        for (int i = 0; i < NA; i++) {
            int slot = tid + i * THREADS;
            int r = slot / (BK / 8);
            int c8 = slot % (BK / 8);
            int row = row0 + r;
            if (CONV_A) {
                float4 f0 = make_float4(0.f, 0.f, 0.f, 0.f), f1 = f0;
                if (row < M) {
                    const float* src = a_f32 + (size_t)row * K + k0 + c8 * 8;
                    f0 = *reinterpret_cast<const float4*>(src);
                    f1 = *reinterpret_cast<const float4*>(src + 4);
                }
                rfa[i][0]=f0.x; rfa[i][1]=f0.y; rfa[i][2]=f0.z; rfa[i][3]=f0.w;
                rfa[i][4]=f1.x; rfa[i][5]=f1.y; rfa[i][6]=f1.z; rfa[i][7]=f1.w;
            } else {
                const __half* A = devbufh(a_id);
                uint4 vh = make_uint4(0,0,0,0);
                if (row < M)
                    vh = *reinterpret_cast<const uint4*>(A + (size_t)row * K + k0 + c8 * 8);
                rha[i] = vh;
            }
        }
        #pragma unroll
        for (int i = 0; i < NB; i++) {
            int slot = tid + i * THREADS;
            int r = slot / (BK / 8);
            int c8 = slot % (BK / 8);
            rhb[i] = *reinterpret_cast<const uint4*>(B + (size_t)(col0 + r) * K + k0 + c8 * 8);
        }
    };

    auto STORE = [&]() {
        #pragma unroll
        for (int i = 0; i < NA; i++) {
            int slot = tid + i * THREADS;
            int r = slot / (BK / 8);
            int c8 = slot % (BK / 8);
            if (CONV_A) {
                __half h[8];
                #pragma unroll
                for (int q = 0; q < 8; q++) h[q] = __float2half_rn(rfa[i][q]);
                *reinterpret_cast<uint4*>(&Ah[r][c8 * 8]) =
                    make_uint4(pack_h2(h[0],h[1]), pack_h2(h[2],h[3]),
                               pack_h2(h[4],h[5]), pack_h2(h[6],h[7]));
            } else {
                *reinterpret_cast<uint4*>(&Ah[r][c8 * 8]) = rha[i];
            }
        }
        #pragma unroll
        for (int i = 0; i < NB; i++) {
            int slot = tid + i * THREADS;
            int r = slot / (BK / 8);
            int c8 = slot % (BK / 8);
            *reinterpret_cast<uint4*>(&Bhs[r][c8 * 8]) = rhb[i];
        }
    };

    LOAD(0);
    STORE();
    __syncthreads();

    for (int t = 0; t < T; t++) {
        if (t + 1 < T) LOAD((t + 1) * BK);

        #pragma unroll
        for (int ks = 0; ks < BK; ks += 16) {
            unsigned ah[MT][4], bh[NT][2];
            #pragma unroll
            for (int mt = 0; mt < MT; mt++) {
                int r = wm * WTM + mt * 16 + (lane & 15);
                int c = ks + ((lane >> 4) << 3);
                ldsm_x4(ah[mt][0], ah[mt][1], ah[mt][2], ah[mt][3],
                        sAh + (unsigned)((r * LDS_ + c) * 2));
            }
            #pragma unroll
            for (int nt = 0; nt < NT; nt++) {
                int r = wn * WTN + nt * 8 + (lane & 7);
                int c = ks + (((lane >> 3) & 1) << 3);
                ldsm_x2(bh[nt][0], bh[nt][1], sBh + (unsigned)((r * LDS_ + c) * 2));
            }
            #pragma unroll
            for (int mt = 0; mt < MT; mt++)
                #pragma unroll
                for (int nt = 0; nt < NT; nt++)
                    mma16816(acc[mt][nt], ah[mt], bh[nt]);
        }
        __syncthreads();
        if (t + 1 < T) {
            STORE();
            __syncthreads();
        }
    }

    __half* Ch = devbufh(hsel ? c1h_id : c0h_id);
    #pragma unroll
    for (int mt = 0; mt < MT; mt++) {
        #pragma unroll
        for (int nt = 0; nt < NT; nt++) {
            int r0 = row0 + wm * WTM + mt * 16 + g;
            int c = col0 + wn * WTN + nt * 8 + tig * 2;
            if (r0 < M)
                *reinterpret_cast<unsigned*>(&Ch[(size_t)r0 * Nh + c]) =
                    pack_h2(__float2half_rn(acc[mt][nt][0]), __float2half_rn(acc[mt][nt][1]));
            if (r0 + 8 < M)
                *reinterpret_cast<unsigned*>(&Ch[(size_t)(r0 + 8) * Nh + c]) =
                    pack_h2(__float2half_rn(acc[mt][nt][2]), __float2half_rn(acc[mt][nt][3]));
        }
    }
}

// ---------------- GATv2 layer 1 aggregation (unchanged from R14 for clean profile) ----------------
__device__ __forceinline__ void load8h(const __half* p, float* v) {
    uint4 u = *reinterpret_cast<const uint4*>(p);
    const __half2* hp = reinterpret_cast<const __half2*>(&u);
    #pragma unroll
    for (int i = 0; i < 4; i++) {
        float2 f = __half22float2(hp[i]);
        v[2 * i] = f.x; v[2 * i + 1] = f.y;
    }
}
__device__ __forceinline__ float score8(const float* v, const float* xrv, const float* attv) {
    float p = 0.f;
    #pragma unroll
    for (int j = 0; j < 8; j++) {
        float t = v[j] + xrv[j];
        t = fmaxf(t, NEG * t);
        p = fmaf(t, attv[j], p);
    }
    p += __shfl_xor_sync(FULLMASK, p, 1);
    p += __shfl_xor_sync(FULLMASK, p, 2);
    return fminf(p, 80.f);
}

__global__ __launch_bounds__(256)
void gat1_agg_kernel(const float* __restrict__ att1, const float* __restrict__ b1) {
    const int wid = threadIdx.x >> 5;
    const int lane = threadIdx.x & 31;
    const int node = blockIdx.x * (blockDim.x >> 5) + wid;
    if (node >= N_NODES) return;

    float attv[8], xrv[8];
    #pragma unroll
    for (int j = 0; j < 8; j++) attv[j] = __ldg(att1 + lane * 8 + j);
    load8h(g_xr1h + (size_t)node * C1 + lane * 8, xrv);

    float d, acc[8];
    {   // self loop
        float v[8];
        load8h(g_xl1h + (size_t)node * C1 + lane * 8, v);
        float f = __expf(score8(v, xrv, attv));
        d = f;
        #pragma unroll
        for (int j = 0; j < 8; j++) acc[j] = f * v[j];
    }

    const int cnt_all = min(g_cnt[node], MAXDEG);
    const int* adj = g_adj + (size_t)node * MAXDEG;
    for (int base = 0; base < cnt_all; base += 32) {
        int sv = 0;
        if (base + lane < cnt_all) sv = adj[base + lane];
        const int cnt = min(32, cnt_all - base);
        int t = 0;
        for (; t + 3 < cnt; t += 4) {
            int sa = __shfl_sync(FULLMASK, sv, t);
            int sb = __shfl_sync(FULLMASK, sv, t + 1);
            int sc = __shfl_sync(FULLMASK, sv, t + 2);
            int sd = __shfl_sync(FULLMASK, sv, t + 3);
            float va[8], vb[8], vc[8], vd[8];
            load8h(g_xl1h + (size_t)sa * C1 + lane * 8, va);
            load8h(g_xl1h + (size_t)sb * C1 + lane * 8, vb);
            load8h(g_xl1h + (size_t)sc * C1 + lane * 8, vc);
            load8h(g_xl1h + (size_t)sd * C1 + lane * 8, vd);
            float fa = __expf(score8(va, xrv, attv));
            float fb = __expf(score8(vb, xrv, attv));
            float fc = __expf(score8(vc, xrv, attv));
            float fd = __expf(score8(vd, xrv, attv));
            d += (fa + fb) + (fc + fd);
            #pragma unroll
            for (int j = 0; j < 8; j++)
                acc[j] = fmaf(fd, vd[j], fmaf(fc, vc[j],
                         fmaf(fb, vb[j], fmaf(fa, va[j], acc[j]))));
        }
        for (; t < cnt; t++) {
            int sa = __shfl_sync(FULLMASK, sv, t);
            float va[8];
            load8h(g_xl1h + (size_t)sa * C1 + lane * 8, va);
            float fa = __expf(score8(va, xrv, attv));
            d += fa;
            #pragma unroll
            for (int j = 0; j < 8; j++) acc[j] = fmaf(fa, va[j], acc[j]);
        }
    }

    const float inv = 1.f / d;
    __half h[8];
    #pragma unroll
    for (int j = 0; j < 8; j++) {
        float hv = fmaf(acc[j], inv, __ldg(b1 + lane * 8 + j));
        hv = (hv > 0.f) ? hv : expm1f(hv);
        h[j] = __float2half_rn(hv);
    }
    *reinterpret_cast<uint4*>(g_h1h + (size_t)node * C1 + lane * 8) =
        make_uint4(pack_h2(h[0],h[1]), pack_h2(h[2],h[3]),
                   pack_h2(h[4],h[5]), pack_h2(h[6],h[7]));
}

// ---------------- preout: out[n,:] = bc + x[n,:] @ Wc[32:160,:] ----------------
__global__ __launch_bounds__(256)
void preout_kernel(const float* __restrict__ x, const float* __restrict__ Wc,
                   const float* __restrict__ bc, float* __restrict__ out) {
    __shared__ float Wt[40][129];
    __shared__ float bcs[40];
    __shared__ float xs[8][128];

    const int tid = threadIdx.x;
    for (int idx = tid; idx < 128 * 40; idx += 256) {
        int k = idx / 40, o = idx % 40;
        Wt[o][k] = Wc[(32 + k) * 40 + o];
    }
    if (tid < 40) bcs[tid] = bc[tid];
    __syncthreads();

    const int wid = tid >> 5;
    const int lane = tid & 31;
    const int node = blockIdx.x * 8 + wid;
    if (node >= N_NODES) return;

    reinterpret_cast<float4*>(xs[wid])[lane] =
        reinterpret_cast<const float4*>(x + (size_t)node * 128)[lane];
    __syncwarp();

    float a0 = bcs[lane];
    float a1 = (lane < 8) ? bcs[32 + lane] : 0.f;
    #pragma unroll 4
    for (int k = 0; k < 128; k++) {
        float xv = xs[wid][k];
        a0 = fmaf(xv, Wt[lane][k], a0);
        if (lane < 8) a1 = fmaf(xv, Wt[32 + lane][k], a1);
    }
    out[(size_t)node * 40 + lane] = a0;
    if (lane < 8) out[(size_t)node * 40 + 32 + lane] = a1;
}

// ---------------- GATv2 layer 2 + h2 @ Wc[0:32,:] + g_cnt reset ----------------
__global__ __launch_bounds__(256)
void gat2_final_kernel(const float* __restrict__ att2, const float* __restrict__ b2,
                       const float* __restrict__ Wc, float* __restrict__ out) {
    __shared__ float Wct[32 * 40];
    __shared__ float h2s[8][33];

    const int tid = threadIdx.x;
    for (int idx = tid; idx < 32 * 40; idx += blockDim.x) Wct[idx] = Wc[idx];
    __syncthreads();

    const int wid = tid >> 5;
    const int lane = tid & 31;
    const int node = blockIdx.x * (blockDim.x >> 5) + wid;
    if (node >= N_NODES) return;

    const float attv = __ldg(att2 + lane);
    const float xr = __half2float(g_xr2h[(size_t)node * C2 + lane]);

    float d, acc;
    {   // self loop
        float v = __half2float(g_xl2h[(size_t)node * C2 + lane]);
        float t = v + xr;
        t = fmaxf(t, NEG * t);
        float p = t * attv;
        #pragma unroll
        for (int o = 16; o; o >>= 1) p += __shfl_xor_sync(FULLMASK, p, o);
        float f = __expf(fminf(p, 80.f));
        d = f; acc = f * v;
    }

    const int cnt_all = min(g_cnt[node], MAXDEG);
    if (lane == 0) g_cnt[node] = 0;   // restore pre-launch state (replay determinism)
    const int* adj = g_adj + (size_t)node * MAXDEG;
    for (int base = 0; base < cnt_all; base += 32) {
        int sv = 0;
        if (base + lane < cnt_all) sv = adj[base + lane];
        const int cnt = min(32, cnt_all - base);
        int t = 0;
        for (; t + 3 < cnt; t += 4) {
            int sa = __shfl_sync(FULLMASK, sv, t);
            int sb = __shfl_sync(FULLMASK, sv, t + 1);
            int sc = __shfl_sync(FULLMASK, sv, t + 2);
            int sd = __shfl_sync(FULLMASK, sv, t + 3);
            float va = __half2float(__ldg(g_xl2h + (size_t)sa * C2 + lane));
            float vb = __half2float(__ldg(g_xl2h + (size_t)sb * C2 + lane));
            float vc = __half2float(__ldg(g_xl2h + (size_t)sc * C2 + lane));
            float vd = __half2float(__ldg(g_xl2h + (size_t)sd * C2 + lane));
            float ta = va + xr; ta = fmaxf(ta, NEG * ta);
            float tb = vb + xr; tb = fmaxf(tb, NEG * tb);
            float tc = vc + xr; tc = fmaxf(tc, NEG * tc);
            float td = vd + xr; td = fmaxf(td, NEG * td);
            float pa = ta * attv, pb = tb * attv, pc = tc * attv, pd = td * attv;
            #pragma unroll
            for (int o = 16; o; o >>= 1) {
                pa += __shfl_xor_sync(FULLMASK, pa, o);
                pb += __shfl_xor_sync(FULLMASK, pb, o);
                pc += __shfl_xor_sync(FULLMASK, pc, o);
                pd += __shfl_xor_sync(FULLMASK, pd, o);
            }
            float fa = __expf(fminf(pa, 80.f));
            float fb = __expf(fminf(pb, 80.f));
            float fc = __expf(fminf(pc, 80.f));
            float fd = __expf(fminf(pd, 80.f));
            d += (fa + fb) + (fc + fd);
            acc = fmaf(fd, vd, fmaf(fc, vc, fmaf(fb, vb, fmaf(fa, va, acc))));
        }
        for (; t < cnt; t++) {
            int sa = __shfl_sync(FULLMASK, sv, t);
            float va = __half2float(__ldg(g_xl2h + (size_t)sa * C2 + lane));
            float ta = va + xr; ta = fmaxf(ta, NEG * ta);
            float pa = ta * attv;
            #pragma unroll
            for (int o = 16; o; o >>= 1) pa += __shfl_xor_sync(FULLMASK, pa, o);
            float fa = __expf(fminf(pa, 80.f));
            d += fa;
            acc = fmaf(fa, va, acc);
        }
    }

    float h2 = fmaf(acc, 1.f / d, __ldg(b2 + lane));
    h2 = (h2 > 0.f) ? h2 : expm1f(h2);
    h2s[wid][lane] = h2;
    __syncwarp();

    float a0 = 0.f, a1 = 0.f;
    #pragma unroll 4
    for (int k = 0; k < 32; k++) {
        float hv = h2s[wid][k];
        a0 = fmaf(hv, Wct[k * 40 + lane], a0);
        if (lane < 8) a1 = fmaf(hv, Wct[k * 40 + 32 + lane], a1);
    }
    out[(size_t)node * 40 + lane] += a0;
    if (lane < 8) out[(size_t)node * 40 + 32 + lane] += a1;
}

// ---------------- launch ----------------
extern "C" void kernel_launch(void* const* d_in, const int* in_sizes, int n_in,
                              void* d_out, int out_size) {
    const float* x    = (const float*)d_in[0];
    const void*  ei   = (const void*)d_in[1];
    const float* W1l  = (const float*)d_in[2];
    const float* W1r  = (const float*)d_in[3];
    const float* att1 = (const float*)d_in[4];
    const float* b1   = (const float*)d_in[5];
    const float* W2l  = (const float*)d_in[6];
    const float* W2r  = (const float*)d_in[7];
    const float* att2 = (const float*)d_in[8];
    const float* b2   = (const float*)d_in[9];
    const float* Wc   = (const float*)d_in[10];
    const float* bc   = (const float*)d_in[11];
    float* out = (float*)d_out;

    static cudaStream_t sB = nullptr, sC = nullptr;
    static cudaEvent_t eF = nullptr, eB = nullptr, eC = nullptr, eW = nullptr;
    if (sB == nullptr) {
        cudaStreamCreateWithFlags(&sB, cudaStreamNonBlocking);
        cudaStreamCreateWithFlags(&sC, cudaStreamNonBlocking);
        cudaEventCreateWithFlags(&eF, cudaEventDisableTiming);
        cudaEventCreateWithFlags(&eB, cudaEventDisableTiming);
        cudaEventCreateWithFlags(&eC, cudaEventDisableTiming);
        cudaEventCreateWithFlags(&eW, cudaEventDisableTiming);
    }

    cudaEventRecord(eF, 0);
    cudaStreamWaitEvent(sB, eF, 0);
    cudaStreamWaitEvent(sC, eF, 0);

    // launch order chosen so gat1_agg is the 4th launch (profiled by ncu).
    convall_kernel<<<(32768 + 8192 + 255) / 256, 256, 0, sC>>>(W1l, W1r, W2l, W2r, ei);  // 1
    cudaEventRecord(eW, sC);

    cudaStreamWaitEvent(sB, eW, 0);   // scatter needs g_is64
    scatter_direct_kernel<<<(N_EDGES + 255) / 256, 256, 0, sB>>>(ei);                    // 2
    cudaEventRecord(eB, sB);

    cudaStreamWaitEvent(0, eW, 0);
    {
        dim3 grid((N_NODES + 127) / 128, (2 * C1) / 128);
        hgemm_dual_kernel<128, 128, 32, 2, 4, 128, true><<<grid, 256>>>(                 // 3
            x, -1, BUFH_B1L, BUFH_B1R, BUFH_XL1H, BUFH_XR1H, N_NODES, C1);
    }

    cudaStreamWaitEvent(0, eB, 0);
    gat1_agg_kernel<<<(N_NODES + 7) / 8, 256>>>(att1, b1);                               // 4 (profiled)

    preout_kernel<<<(N_NODES + 7) / 8, 256, 0, sC>>>(x, Wc, bc, out);                    // 5
    cudaEventRecord(eC, sC);

    {
        dim3 grid((N_NODES + 127) / 128, (2 * C2) / 32);
        hgemm_dual_kernel<128, 32, 64, 4, 1, 256, false><<<grid, 128>>>(                 // 6
            nullptr, BUFH_H1H, BUFH_B2L, BUFH_B2R, BUFH_XL2H, BUFH_XR2H, N_NODES, C2);
    }

    cudaStreamWaitEvent(0, eC, 0);
    gat2_final_kernel<<<(N_NODES + 7) / 8, 256>>>(att2, b2, Wc, out);                    // 7
}

// round 16
// speedup vs baseline: 1.2616x; 1.2616x over previous
#include <cuda_runtime.h>
#include <cuda_fp16.h>
#include <math.h>

#define N_NODES 50000
#define N_EDGES 800000
#define C1 256
#define C2 32
#define NEG 0.2f
#define FULLMASK 0xffffffffu
#define MAXDEG 128

// ---------------- scratch ----------------
__device__ __align__(16) __half g_xr1h[(size_t)N_NODES * C1];
__device__ __align__(16) __half g_xr2h[(size_t)N_NODES * C2];
__device__ __align__(16) __half g_xl1h[(size_t)N_NODES * C1];
__device__ __align__(16) __half g_xl2h[(size_t)N_NODES * C2];
__device__ __align__(16) __half g_h1h[(size_t)N_NODES * C1];
__device__ __align__(16) __half g_b1l[(size_t)C1 * 128];
__device__ __align__(16) __half g_b1r[(size_t)C1 * 128];
__device__ __align__(16) __half g_b2l[(size_t)C2 * 256];
__device__ __align__(16) __half g_b2r[(size_t)C2 * 256];
__device__ __align__(16) int    g_cnt[N_NODES];
__device__ __align__(16) int    g_adj[(size_t)N_NODES * MAXDEG];
__device__ int g_is64;

#define BUFH_B1L  0
#define BUFH_B1R  1
#define BUFH_H1H  2
#define BUFH_B2L  3
#define BUFH_B2R  4
#define BUFH_XL1H 5
#define BUFH_XL2H 6
#define BUFH_XR1H 7
#define BUFH_XR2H 8
__device__ __forceinline__ __half* devbufh(int id) {
    switch (id) {
        case BUFH_B1L:  return g_b1l;
        case BUFH_B1R:  return g_b1r;
        case BUFH_H1H:  return g_h1h;
        case BUFH_B2L:  return g_b2l;
        case BUFH_B2R:  return g_b2r;
        case BUFH_XL1H: return g_xl1h;
        case BUFH_XL2H: return g_xl2h;
        case BUFH_XR1H: return g_xr1h;
        default:        return g_xr2h;
    }
}

__device__ __forceinline__ unsigned pack_h2(__half a, __half b) {
    __half2 p = __halves2half2(a, b);
    return *reinterpret_cast<unsigned*>(&p);
}

// ---------------- init: edge dtype detect + zero counters (fused) ----------------
__global__ void init_kernel(const void* __restrict__ ei) {
    int i = blockIdx.x * blockDim.x + threadIdx.x;
    if (i < N_NODES) g_cnt[i] = 0;
    if (i == 0) {
        const unsigned long long* p = (const unsigned long long*)ei;
        int ok = 1;
        for (int q = 0; q < 64; q++)
            if (p[q] >> 32) { ok = 0; break; }
        g_is64 = ok;
    }
}

__device__ __forceinline__ int edge_at(const void* __restrict__ ei, int row, int e) {
    if (g_is64) return (int)((const long long*)ei)[(size_t)row * N_EDGES + e];
    return ((const int*)ei)[(size_t)row * N_EDGES + e];
}

// ---------------- direct padded-CSR scatter ----------------
__global__ void scatter_direct_kernel(const void* __restrict__ ei) {
    int e = blockIdx.x * blockDim.x + threadIdx.x;
    if (e < N_EDGES) {
        int src = edge_at(ei, 0, e);
        int dst = edge_at(ei, 1, e);
        src = min(max(src, 0), N_NODES - 1);
        dst = min(max(dst, 0), N_NODES - 1);
        int slot = atomicAdd(&g_cnt[dst], 1);
        if (slot < MAXDEG)
            g_adj[(size_t)dst * MAXDEG + slot] = src;
    }
}

// ---------------- weight conversion: W [K,N] fp32 -> [N][K] fp16 ----------------
__global__ void conv_w_kernel(const float* __restrict__ W, int out_id, int K, int N) {
    int idx = blockIdx.x * blockDim.x + threadIdx.x;
    if (idx >= N * K) return;
    int n = idx / K, k = idx % K;
    devbufh(out_id)[(size_t)n * K + k] = __float2half_rn(W[(size_t)k * N + n]);
}

// ---------------- fp16 tensor-core dual GEMM (both outputs fp16) ----------------
__device__ __forceinline__ void mma16816(float* c, const unsigned* a, const unsigned* b) {
    asm volatile(
        "mma.sync.aligned.m16n8k16.row.col.f32.f16.f16.f32 "
        "{%0,%1,%2,%3}, {%4,%5,%6,%7}, {%8,%9}, {%0,%1,%2,%3};"
        : "+f"(c[0]), "+f"(c[1]), "+f"(c[2]), "+f"(c[3])
        : "r"(a[0]), "r"(a[1]), "r"(a[2]), "r"(a[3]), "r"(b[0]), "r"(b[1]));
}
__device__ __forceinline__ void ldsm_x4(unsigned& r0, unsigned& r1, unsigned& r2, unsigned& r3,
                                        unsigned addr) {
    asm volatile("ldmatrix.sync.aligned.m8n8.x4.shared.b16 {%0,%1,%2,%3}, [%4];"
                 : "=r"(r0), "=r"(r1), "=r"(r2), "=r"(r3) : "r"(addr));
}
__device__ __forceinline__ void ldsm_x2(unsigned& r0, unsigned& r1, unsigned addr) {
    asm volatile("ldmatrix.sync.aligned.m8n8.x2.shared.b16 {%0,%1}, [%2];"
                 : "=r"(r0), "=r"(r1) : "r"(addr));
}

template <int BM, int BN, int BK, int WM, int WN, int K, bool CONV_A>
__global__ __launch_bounds__(WM * WN * 32, 2)
void hgemm_dual_kernel(const float* __restrict__ a_f32, int a_id,
                       int b0_id, int b1_id, int c0h_id, int c1h_id,
                       int M, int Nh) {
    constexpr int THREADS = WM * WN * 32;
    constexpr int WTM = BM / WM;
    constexpr int WTN = BN / WN;
    constexpr int MT = WTM / 16;
    constexpr int NT = WTN / 8;
    constexpr int LDS_ = BK + 8;
    constexpr int T = K / BK;
    constexpr int NA = (BM * BK / 8) / THREADS;
    constexpr int NB = (BN * BK / 8) / THREADS;

    __shared__ __half Ah[BM][LDS_];
    __shared__ __half Bhs[BN][LDS_];

    const int colL = blockIdx.y * BN;
    const int hsel = (colL >= Nh) ? 1 : 0;
    const __half* B = devbufh(hsel ? b1_id : b0_id);
    const int col0 = colL - hsel * Nh;

    const int tid = threadIdx.x;
    const int row0 = blockIdx.x * BM;
    const int wid = tid >> 5;
    const int lane = tid & 31;
    const int wm = wid / WN, wn = wid % WN;
    const int g = lane >> 2, tig = lane & 3;

    const unsigned sAh = (unsigned)__cvta_generic_to_shared(&Ah[0][0]);
    const unsigned sBh = (unsigned)__cvta_generic_to_shared(&Bhs[0][0]);

    float acc[MT][NT][4];
    #pragma unroll
    for (int i = 0; i < MT; i++)
        #pragma unroll
        for (int j = 0; j < NT; j++)
            #pragma unroll
            for (int q = 0; q < 4; q++) acc[i][j][q] = 0.f;

    float rfa[NA][8];
    uint4 rha[NA];
    uint4 rhb[NB];

    auto LOAD = [&](int k0) {
        #pragma unroll
        for (int i = 0; i < NA; i++) {
            int slot = tid + i * THREADS;
            int r = slot / (BK / 8);
            int c8 = slot % (BK / 8);
            int row = row0 + r;
            if (CONV_A) {
                float4 f0 = make_float4(0.f, 0.f, 0.f, 0.f), f1 = f0;
                if (row < M) {
                    const float* src = a_f32 + (size_t)row * K + k0 + c8 * 8;
                    f0 = *reinterpret_cast<const float4*>(src);
                    f1 = *reinterpret_cast<const float4*>(src + 4);
                }
                rfa[i][0]=f0.x; rfa[i][1]=f0.y; rfa[i][2]=f0.z; rfa[i][3]=f0.w;
                rfa[i][4]=f1.x; rfa[i][5]=f1.y; rfa[i][6]=f1.z; rfa[i][7]=f1.w;
            } else {
                const __half* A = devbufh(a_id);
                uint4 vh = make_uint4(0,0,0,0);
                if (row < M)
                    vh = *reinterpret_cast<const uint4*>(A + (size_t)row * K + k0 + c8 * 8);
                rha[i] = vh;
            }
        }
        #pragma unroll
        for (int i = 0; i < NB; i++) {
            int slot = tid + i * THREADS;
            int r = slot / (BK / 8);
            int c8 = slot % (BK / 8);
            rhb[i] = *reinterpret_cast<const uint4*>(B + (size_t)(col0 + r) * K + k0 + c8 * 8);
        }
    };

    auto STORE = [&]() {
        #pragma unroll
        for (int i = 0; i < NA; i++) {
            int slot = tid + i * THREADS;
            int r = slot / (BK / 8);
            int c8 = slot % (BK / 8);
            if (CONV_A) {
                __half h[8];
                #pragma unroll
                for (int q = 0; q < 8; q++) h[q] = __float2half_rn(rfa[i][q]);
                *reinterpret_cast<uint4*>(&Ah[r][c8 * 8]) =
                    make_uint4(pack_h2(h[0],h[1]), pack_h2(h[2],h[3]),
                               pack_h2(h[4],h[5]), pack_h2(h[6],h[7]));
            } else {
                *reinterpret_cast<uint4*>(&Ah[r][c8 * 8]) = rha[i];
            }
        }
        #pragma unroll
        for (int i = 0; i < NB; i++) {
            int slot = tid + i * THREADS;
            int r = slot / (BK / 8);
            int c8 = slot % (BK / 8);
            *reinterpret_cast<uint4*>(&Bhs[r][c8 * 8]) = rhb[i];
        }
    };

    LOAD(0);
    STORE();
    __syncthreads();

    for (int t = 0; t < T; t++) {
        if (t + 1 < T) LOAD((t + 1) * BK);

        #pragma unroll
        for (int ks = 0; ks < BK; ks += 16) {
            unsigned ah[MT][4], bh[NT][2];
            #pragma unroll
            for (int mt = 0; mt < MT; mt++) {
                int r = wm * WTM + mt * 16 + (lane & 15);
                int c = ks + ((lane >> 4) << 3);
                ldsm_x4(ah[mt][0], ah[mt][1], ah[mt][2], ah[mt][3],
                        sAh + (unsigned)((r * LDS_ + c) * 2));
            }
            #pragma unroll
            for (int nt = 0; nt < NT; nt++) {
                int r = wn * WTN + nt * 8 + (lane & 7);
                int c = ks + (((lane >> 3) & 1) << 3);
                ldsm_x2(bh[nt][0], bh[nt][1], sBh + (unsigned)((r * LDS_ + c) * 2));
            }
            #pragma unroll
            for (int mt = 0; mt < MT; mt++)
                #pragma unroll
                for (int nt = 0; nt < NT; nt++)
                    mma16816(acc[mt][nt], ah[mt], bh[nt]);
        }
        __syncthreads();
        if (t + 1 < T) {
            STORE();
            __syncthreads();
        }
    }

    __half* Ch = devbufh(hsel ? c1h_id : c0h_id);
    #pragma unroll
    for (int mt = 0; mt < MT; mt++) {
        #pragma unroll
        for (int nt = 0; nt < NT; nt++) {
            int r0 = row0 + wm * WTM + mt * 16 + g;
            int c = col0 + wn * WTN + nt * 8 + tig * 2;
            if (r0 < M)
                *reinterpret_cast<unsigned*>(&Ch[(size_t)r0 * Nh + c]) =
                    pack_h2(__float2half_rn(acc[mt][nt][0]), __float2half_rn(acc[mt][nt][1]));
            if (r0 + 8 < M)
                *reinterpret_cast<unsigned*>(&Ch[(size_t)(r0 + 8) * Nh + c]) =
                    pack_h2(__float2half_rn(acc[mt][nt][2]), __float2half_rn(acc[mt][nt][3]));
        }
    }
}

// ---------------- GATv2 layer 1 aggregation (half2 score math) ----------------
// score in packed half2 (HADD2/HMUL2/HMAX2/HFMA2), accumulate in fp32.
__device__ __forceinline__ float score_h2(const uint4& u, const __half2* xr2,
                                          const __half2* att2, const __half2 neg2) {
    const __half2* vh = reinterpret_cast<const __half2*>(&u);
    __half2 p2 = __float2half2_rn(0.f);
    #pragma unroll
    for (int j = 0; j < 4; j++) {
        __half2 t = __hadd2(vh[j], xr2[j]);
        t = __hmax2(t, __hmul2(neg2, t));
        p2 = __hfma2(t, att2[j], p2);
    }
    float2 pf = __half22float2(p2);
    float p = pf.x + pf.y;
    p += __shfl_xor_sync(FULLMASK, p, 1);
    p += __shfl_xor_sync(FULLMASK, p, 2);
    return fminf(p, 80.f);
}
__device__ __forceinline__ void acc_h2(float* acc, const uint4& u, float f) {
    const __half2* vh = reinterpret_cast<const __half2*>(&u);
    #pragma unroll
    for (int j = 0; j < 4; j++) {
        float2 fv = __half22float2(vh[j]);
        acc[2 * j]     = fmaf(f, fv.x, acc[2 * j]);
        acc[2 * j + 1] = fmaf(f, fv.y, acc[2 * j + 1]);
    }
}

__global__ __launch_bounds__(256)
void gat1_agg_kernel(const float* __restrict__ att1, const float* __restrict__ b1) {
    const int wid = threadIdx.x >> 5;
    const int lane = threadIdx.x & 31;
    const int node = blockIdx.x * (blockDim.x >> 5) + wid;
    if (node >= N_NODES) return;

    __half2 att2[4], xr2[4];
    #pragma unroll
    for (int j = 0; j < 4; j++)
        att2[j] = __floats2half2_rn(__ldg(att1 + lane * 8 + 2 * j),
                                    __ldg(att1 + lane * 8 + 2 * j + 1));
    {
        uint4 uxr = *reinterpret_cast<const uint4*>(g_xr1h + (size_t)node * C1 + lane * 8);
        const __half2* p = reinterpret_cast<const __half2*>(&uxr);
        #pragma unroll
        for (int j = 0; j < 4; j++) xr2[j] = p[j];
    }
    const __half2 neg2 = __float2half2_rn(NEG);

    float d, acc[8];
    #pragma unroll
    for (int j = 0; j < 8; j++) acc[j] = 0.f;
    {   // self loop
        uint4 u = *reinterpret_cast<const uint4*>(g_xl1h + (size_t)node * C1 + lane * 8);
        float f = __expf(score_h2(u, xr2, att2, neg2));
        d = f;
        acc_h2(acc, u, f);
    }

    const int cnt_all = min(g_cnt[node], MAXDEG);
    const int* adj = g_adj + (size_t)node * MAXDEG;
    for (int base = 0; base < cnt_all; base += 32) {
        int sv = 0;
        if (base + lane < cnt_all) sv = adj[base + lane];
        const int cnt = min(32, cnt_all - base);
        int t = 0;
        for (; t + 3 < cnt; t += 4) {
            int sa = __shfl_sync(FULLMASK, sv, t);
            int sb = __shfl_sync(FULLMASK, sv, t + 1);
            int sc = __shfl_sync(FULLMASK, sv, t + 2);
            int sd = __shfl_sync(FULLMASK, sv, t + 3);
            uint4 ua = *reinterpret_cast<const uint4*>(g_xl1h + (size_t)sa * C1 + lane * 8);
            uint4 ub = *reinterpret_cast<const uint4*>(g_xl1h + (size_t)sb * C1 + lane * 8);
            uint4 uc = *reinterpret_cast<const uint4*>(g_xl1h + (size_t)sc * C1 + lane * 8);
            uint4 ud = *reinterpret_cast<const uint4*>(g_xl1h + (size_t)sd * C1 + lane * 8);
            float fa = __expf(score_h2(ua, xr2, att2, neg2));
            float fb = __expf(score_h2(ub, xr2, att2, neg2));
            float fc = __expf(score_h2(uc, xr2, att2, neg2));
            float fd = __expf(score_h2(ud, xr2, att2, neg2));
            d += (fa + fb) + (fc + fd);
            acc_h2(acc, ua, fa);
            acc_h2(acc, ub, fb);
            acc_h2(acc, uc, fc);
            acc_h2(acc, ud, fd);
        }
        for (; t < cnt; t++) {
            int sa = __shfl_sync(FULLMASK, sv, t);
            uint4 ua = *reinterpret_cast<const uint4*>(g_xl1h + (size_t)sa * C1 + lane * 8);
            float fa = __expf(score_h2(ua, xr2, att2, neg2));
            d += fa;
            acc_h2(acc, ua, fa);
        }
    }

    const float inv = 1.f / d;
    __half h[8];
    #pragma unroll
    for (int j = 0; j < 8; j++) {
        float hv = fmaf(acc[j], inv, __ldg(b1 + lane * 8 + j));
        hv = (hv > 0.f) ? hv : expm1f(hv);
        h[j] = __float2half_rn(hv);
    }
    *reinterpret_cast<uint4*>(g_h1h + (size_t)node * C1 + lane * 8) =
        make_uint4(pack_h2(h[0],h[1]), pack_h2(h[2],h[3]),
                   pack_h2(h[4],h[5]), pack_h2(h[6],h[7]));
}

// ---------------- preout: out[n,:] = bc + x[n,:] @ Wc[32:160,:] ----------------
__global__ __launch_bounds__(256)
void preout_kernel(const float* __restrict__ x, const float* __restrict__ Wc,
                   const float* __restrict__ bc, float* __restrict__ out) {
    __shared__ float Wt[40][129];
    __shared__ float bcs[40];
    __shared__ float xs[8][128];

    const int tid = threadIdx.x;
    for (int idx = tid; idx < 128 * 40; idx += 256) {
        int k = idx / 40, o = idx % 40;
        Wt[o][k] = Wc[(32 + k) * 40 + o];
    }
    if (tid < 40) bcs[tid] = bc[tid];
    __syncthreads();

    const int wid = tid >> 5;
    const int lane = tid & 31;
    const int node = blockIdx.x * 8 + wid;
    if (node >= N_NODES) return;

    reinterpret_cast<float4*>(xs[wid])[lane] =
        reinterpret_cast<const float4*>(x + (size_t)node * 128)[lane];
    __syncwarp();

    float a0 = bcs[lane];
    float a1 = (lane < 8) ? bcs[32 + lane] : 0.f;
    #pragma unroll 4
    for (int k = 0; k < 128; k++) {
        float xv = xs[wid][k];
        a0 = fmaf(xv, Wt[lane][k], a0);
        if (lane < 8) a1 = fmaf(xv, Wt[32 + lane][k], a1);
    }
    out[(size_t)node * 40 + lane] = a0;
    if (lane < 8) out[(size_t)node * 40 + 32 + lane] = a1;
}

// ---------------- GATv2 layer 2 + h2 @ Wc[0:32,:] ----------------
__global__ __launch_bounds__(256)
void gat2_final_kernel(const float* __restrict__ att2, const float* __restrict__ b2,
                       const float* __restrict__ Wc, float* __restrict__ out) {
    __shared__ float Wct[32 * 40];
    __shared__ float h2s[8][33];

    const int tid = threadIdx.x;
    for (int idx = tid; idx < 32 * 40; idx += blockDim.x) Wct[idx] = Wc[idx];
    __syncthreads();

    const int wid = tid >> 5;
    const int lane = tid & 31;
    const int node = blockIdx.x * (blockDim.x >> 5) + wid;
    if (node >= N_NODES) return;

    const float attv = __ldg(att2 + lane);
    const float xr = __half2float(g_xr2h[(size_t)node * C2 + lane]);

    float d, acc;
    {   // self loop
        float v = __half2float(g_xl2h[(size_t)node * C2 + lane]);
        float t = v + xr;
        t = fmaxf(t, NEG * t);
        float p = t * attv;
        #pragma unroll
        for (int o = 16; o; o >>= 1) p += __shfl_xor_sync(FULLMASK, p, o);
        float f = __expf(fminf(p, 80.f));
        d = f; acc = f * v;
    }

    const int cnt_all = min(g_cnt[node], MAXDEG);
    const int* adj = g_adj + (size_t)node * MAXDEG;
    for (int base = 0; base < cnt_all; base += 32) {
        int sv = 0;
        if (base + lane < cnt_all) sv = adj[base + lane];
        const int cnt = min(32, cnt_all - base);
        int t = 0;
        for (; t + 3 < cnt; t += 4) {
            int sa = __shfl_sync(FULLMASK, sv, t);
            int sb = __shfl_sync(FULLMASK, sv, t + 1);
            int sc = __shfl_sync(FULLMASK, sv, t + 2);
            int sd = __shfl_sync(FULLMASK, sv, t + 3);
            float va = __half2float(__ldg(g_xl2h + (size_t)sa * C2 + lane));
            float vb = __half2float(__ldg(g_xl2h + (size_t)sb * C2 + lane));
            float vc = __half2float(__ldg(g_xl2h + (size_t)sc * C2 + lane));
            float vd = __half2float(__ldg(g_xl2h + (size_t)sd * C2 + lane));
            float ta = va + xr; ta = fmaxf(ta, NEG * ta);
            float tb = vb + xr; tb = fmaxf(tb, NEG * tb);
            float tc = vc + xr; tc = fmaxf(tc, NEG * tc);
            float td = vd + xr; td = fmaxf(td, NEG * td);
            float pa = ta * attv, pb = tb * attv, pc = tc * attv, pd = td * attv;
            #pragma unroll
            for (int o = 16; o; o >>= 1) {
                pa += __shfl_xor_sync(FULLMASK, pa, o);
                pb += __shfl_xor_sync(FULLMASK, pb, o);
                pc += __shfl_xor_sync(FULLMASK, pc, o);
                pd += __shfl_xor_sync(FULLMASK, pd, o);
            }
            float fa = __expf(fminf(pa, 80.f));
            float fb = __expf(fminf(pb, 80.f));
            float fc = __expf(fminf(pc, 80.f));
            float fd = __expf(fminf(pd, 80.f));
            d += (fa + fb) + (fc + fd);
            acc = fmaf(fd, vd, fmaf(fc, vc, fmaf(fb, vb, fmaf(fa, va, acc))));
        }
        for (; t < cnt; t++) {
            int sa = __shfl_sync(FULLMASK, sv, t);
            float va = __half2float(__ldg(g_xl2h + (size_t)sa * C2 + lane));
            float ta = va + xr; ta = fmaxf(ta, NEG * ta);
            float pa = ta * attv;
            #pragma unroll
            for (int o = 16; o; o >>= 1) pa += __shfl_xor_sync(FULLMASK, pa, o);
            float fa = __expf(fminf(pa, 80.f));
            d += fa;
            acc = fmaf(fa, va, acc);
        }
    }

    float h2 = fmaf(acc, 1.f / d, __ldg(b2 + lane));
    h2 = (h2 > 0.f) ? h2 : expm1f(h2);
    h2s[wid][lane] = h2;
    __syncwarp();

    float a0 = 0.f, a1 = 0.f;
    #pragma unroll 4
    for (int k = 0; k < 32; k++) {
        float hv = h2s[wid][k];
        a0 = fmaf(hv, Wct[k * 40 + lane], a0);
        if (lane < 8) a1 = fmaf(hv, Wct[k * 40 + 32 + lane], a1);
    }
    out[(size_t)node * 40 + lane] += a0;
    if (lane < 8) out[(size_t)node * 40 + 32 + lane] += a1;
}

// ---------------- launch (R14 topology restored) ----------------
extern "C" void kernel_launch(void* const* d_in, const int* in_sizes, int n_in,
                              void* d_out, int out_size) {
    const float* x    = (const float*)d_in[0];
    const void*  ei   = (const void*)d_in[1];
    const float* W1l  = (const float*)d_in[2];
    const float* W1r  = (const float*)d_in[3];
    const float* att1 = (const float*)d_in[4];
    const float* b1   = (const float*)d_in[5];
    const float* W2l  = (const float*)d_in[6];
    const float* W2r  = (const float*)d_in[7];
    const float* att2 = (const float*)d_in[8];
    const float* b2   = (const float*)d_in[9];
    const float* Wc   = (const float*)d_in[10];
    const float* bc   = (const float*)d_in[11];
    float* out = (float*)d_out;

    static cudaStream_t sB = nullptr, sC = nullptr;
    static cudaEvent_t eF = nullptr, eB = nullptr, eC = nullptr, eW = nullptr;
    if (sB == nullptr) {
        cudaStreamCreateWithFlags(&sB, cudaStreamNonBlocking);
        cudaStreamCreateWithFlags(&sC, cudaStreamNonBlocking);
        cudaEventCreateWithFlags(&eF, cudaEventDisableTiming);
        cudaEventCreateWithFlags(&eB, cudaEventDisableTiming);
        cudaEventCreateWithFlags(&eC, cudaEventDisableTiming);
        cudaEventCreateWithFlags(&eW, cudaEventDisableTiming);
    }

    cudaEventRecord(eF, 0);
    cudaStreamWaitEvent(sB, eF, 0);
    cudaStreamWaitEvent(sC, eF, 0);

    init_kernel<<<(N_NODES + 255) / 256, 256, 0, sB>>>(ei);                          // 1
    conv_w_kernel<<<(C1 * 128 + 255) / 256, 256, 0, sC>>>(W1l, BUFH_B1L, 128, C1);   // 2
    conv_w_kernel<<<(C1 * 128 + 255) / 256, 256, 0, sC>>>(W1r, BUFH_B1R, 128, C1);   // 3
    cudaEventRecord(eW, sC);

    cudaStreamWaitEvent(0, eW, 0);
    {
        dim3 grid((N_NODES + 127) / 128, (2 * C1) / 128);
        hgemm_dual_kernel<128, 128, 32, 2, 4, 128, true><<<grid, 256>>>(             // 4 (profiled)
            x, -1, BUFH_B1L, BUFH_B1R, BUFH_XL1H, BUFH_XR1H, N_NODES, C1);
    }

    scatter_direct_kernel<<<(N_EDGES + 255) / 256, 256, 0, sB>>>(ei);
    cudaEventRecord(eB, sB);

    conv_w_kernel<<<(C2 * 256 + 255) / 256, 256, 0, sC>>>(W2l, BUFH_B2L, 256, C2);
    conv_w_kernel<<<(C2 * 256 + 255) / 256, 256, 0, sC>>>(W2r, BUFH_B2R, 256, C2);
    preout_kernel<<<(N_NODES + 7) / 8, 256, 0, sC>>>(x, Wc, bc, out);
    cudaEventRecord(eC, sC);

    cudaStreamWaitEvent(0, eB, 0);
    gat1_agg_kernel<<<(N_NODES + 7) / 8, 256>>>(att1, b1);

    {
        dim3 grid((N_NODES + 127) / 128, (2 * C2) / 32);
        hgemm_dual_kernel<128, 32, 64, 4, 1, 256, false><<<grid, 128>>>(
            nullptr, BUFH_H1H, BUFH_B2L, BUFH_B2R, BUFH_XL2H, BUFH_XR2H, N_NODES, C2);
    }

    cudaStreamWaitEvent(0, eC, 0);
    gat2_final_kernel<<<(N_NODES + 7) / 8, 256>>>(att2, b2, Wc, out);
}

// round 17
// speedup vs baseline: 1.2647x; 1.0024x over previous
#include <cuda_runtime.h>
#include <cuda_fp16.h>
#include <math.h>

#define N_NODES 50000
#define N_EDGES 800000
#define C1 256
#define C2 32
#define NEG 0.2f
#define FULLMASK 0xffffffffu
#define MAXDEG 128
#define NHALF 25088   // gat1/GEMM2 pipeline split (multiple of 128)

// ---------------- scratch ----------------
__device__ __align__(16) __half g_xr1h[(size_t)N_NODES * C1];
__device__ __align__(16) __half g_xr2h[(size_t)N_NODES * C2];
__device__ __align__(16) __half g_xl1h[(size_t)N_NODES * C1];
__device__ __align__(16) __half g_xl2h[(size_t)N_NODES * C2];
__device__ __align__(16) __half g_h1h[(size_t)N_NODES * C1];
__device__ __align__(16) __half g_b1l[(size_t)C1 * 128];
__device__ __align__(16) __half g_b1r[(size_t)C1 * 128];
__device__ __align__(16) __half g_b2l[(size_t)C2 * 256];
__device__ __align__(16) __half g_b2r[(size_t)C2 * 256];
__device__ __align__(16) int    g_cnt[N_NODES];
__device__ __align__(16) int    g_adj[(size_t)N_NODES * MAXDEG];
__device__ int g_is64;

#define BUFH_B1L  0
#define BUFH_B1R  1
#define BUFH_H1H  2
#define BUFH_B2L  3
#define BUFH_B2R  4
#define BUFH_XL1H 5
#define BUFH_XL2H 6
#define BUFH_XR1H 7
#define BUFH_XR2H 8
__device__ __forceinline__ __half* devbufh(int id) {
    switch (id) {
        case BUFH_B1L:  return g_b1l;
        case BUFH_B1R:  return g_b1r;
        case BUFH_H1H:  return g_h1h;
        case BUFH_B2L:  return g_b2l;
        case BUFH_B2R:  return g_b2r;
        case BUFH_XL1H: return g_xl1h;
        case BUFH_XL2H: return g_xl2h;
        case BUFH_XR1H: return g_xr1h;
        default:        return g_xr2h;
    }
}

__device__ __forceinline__ unsigned pack_h2(__half a, __half b) {
    __half2 p = __halves2half2(a, b);
    return *reinterpret_cast<unsigned*>(&p);
}
__device__ __forceinline__ __half2 shfl_xor_h2(__half2 v, int m) {
    unsigned u = *reinterpret_cast<unsigned*>(&v);
    u = __shfl_xor_sync(FULLMASK, u, m);
    return *reinterpret_cast<__half2*>(&u);
}

// ---------------- init ----------------
__global__ void init_kernel(const void* __restrict__ ei) {
    int i = blockIdx.x * blockDim.x + threadIdx.x;
    if (i < N_NODES) g_cnt[i] = 0;
    if (i == 0) {
        const unsigned long long* p = (const unsigned long long*)ei;
        int ok = 1;
        for (int q = 0; q < 64; q++)
            if (p[q] >> 32) { ok = 0; break; }
        g_is64 = ok;
    }
}

__device__ __forceinline__ int edge_at(const void* __restrict__ ei, int row, int e) {
    if (g_is64) return (int)((const long long*)ei)[(size_t)row * N_EDGES + e];
    return ((const int*)ei)[(size_t)row * N_EDGES + e];
}

__global__ void scatter_direct_kernel(const void* __restrict__ ei) {
    int e = blockIdx.x * blockDim.x + threadIdx.x;
    if (e < N_EDGES) {
        int src = edge_at(ei, 0, e);
        int dst = edge_at(ei, 1, e);
        src = min(max(src, 0), N_NODES - 1);
        dst = min(max(dst, 0), N_NODES - 1);
        int slot = atomicAdd(&g_cnt[dst], 1);
        if (slot < MAXDEG)
            g_adj[(size_t)dst * MAXDEG + slot] = src;
    }
}

__global__ void conv_w_kernel(const float* __restrict__ W, int out_id, int K, int N) {
    int idx = blockIdx.x * blockDim.x + threadIdx.x;
    if (idx >= N * K) return;
    int n = idx / K, k = idx % K;
    devbufh(out_id)[(size_t)n * K + k] = __float2half_rn(W[(size_t)k * N + n]);
}

// ---------------- fp16 tensor-core dual GEMM (rowBase for pipelining) ----------------
__device__ __forceinline__ void mma16816(float* c, const unsigned* a, const unsigned* b) {
    asm volatile(
        "mma.sync.aligned.m16n8k16.row.col.f32.f16.f16.f32 "
        "{%0,%1,%2,%3}, {%4,%5,%6,%7}, {%8,%9}, {%0,%1,%2,%3};"
        : "+f"(c[0]), "+f"(c[1]), "+f"(c[2]), "+f"(c[3])
        : "r"(a[0]), "r"(a[1]), "r"(a[2]), "r"(a[3]), "r"(b[0]), "r"(b[1]));
}
__device__ __forceinline__ void ldsm_x4(unsigned& r0, unsigned& r1, unsigned& r2, unsigned& r3,
                                        unsigned addr) {
    asm volatile("ldmatrix.sync.aligned.m8n8.x4.shared.b16 {%0,%1,%2,%3}, [%4];"
                 : "=r"(r0), "=r"(r1), "=r"(r2), "=r"(r3) : "r"(addr));
}
__device__ __forceinline__ void ldsm_x2(unsigned& r0, unsigned& r1, unsigned addr) {
    asm volatile("ldmatrix.sync.aligned.m8n8.x2.shared.b16 {%0,%1}, [%2];"
                 : "=r"(r0), "=r"(r1) : "r"(addr));
}

template <int BM, int BN, int BK, int WM, int WN, int K, bool CONV_A>
__global__ __launch_bounds__(WM * WN * 32, 2)
void hgemm_dual_kernel(const float* __restrict__ a_f32, int a_id,
                       int b0_id, int b1_id, int c0h_id, int c1h_id,
                       int M, int Nh, int rowBase) {
    constexpr int THREADS = WM * WN * 32;
    constexpr int WTM = BM / WM;
    constexpr int WTN = BN / WN;
    constexpr int MT = WTM / 16;
    constexpr int NT = WTN / 8;
    constexpr int LDS_ = BK + 8;
    constexpr int T = K / BK;
    constexpr int NA = (BM * BK / 8) / THREADS;
    constexpr int NB = (BN * BK / 8) / THREADS;

    __shared__ __half Ah[BM][LDS_];
    __shared__ __half Bhs[BN][LDS_];

    const int colL = blockIdx.y * BN;
    const int hsel = (colL >= Nh) ? 1 : 0;
    const __half* B = devbufh(hsel ? b1_id : b0_id);
    const int col0 = colL - hsel * Nh;

    const int tid = threadIdx.x;
    const int row0 = rowBase + blockIdx.x * BM;
    const int wid = tid >> 5;
    const int lane = tid & 31;
    const int wm = wid / WN, wn = wid % WN;
    const int g = lane >> 2, tig = lane & 3;

    const unsigned sAh = (unsigned)__cvta_generic_to_shared(&Ah[0][0]);
    const unsigned sBh = (unsigned)__cvta_generic_to_shared(&Bhs[0][0]);

    float acc[MT][NT][4];
    #pragma unroll
    for (int i = 0; i < MT; i++)
        #pragma unroll
        for (int j = 0; j < NT; j++)
            #pragma unroll
            for (int q = 0; q < 4; q++) acc[i][j][q] = 0.f;

    float rfa[NA][8];
    uint4 rha[NA];
    uint4 rhb[NB];

    auto LOAD = [&](int k0) {
        #pragma unroll
        for (int i = 0; i < NA; i++) {
            int slot = tid + i * THREADS;
            int r = slot / (BK / 8);
            int c8 = slot % (BK / 8);
            int row = row0 + r;
            if (CONV_A) {
                float4 f0 = make_float4(0.f, 0.f, 0.f, 0.f), f1 = f0;
                if (row < M) {
                    const float* src = a_f32 + (size_t)row * K + k0 + c8 * 8;
                    f0 = *reinterpret_cast<const float4*>(src);
                    f1 = *reinterpret_cast<const float4*>(src + 4);
                }
                rfa[i][0]=f0.x; rfa[i][1]=f0.y; rfa[i][2]=f0.z; rfa[i][3]=f0.w;
                rfa[i][4]=f1.x; rfa[i][5]=f1.y; rfa[i][6]=f1.z; rfa[i][7]=f1.w;
            } else {
                const __half* A = devbufh(a_id);
                uint4 vh = make_uint4(0,0,0,0);
                if (row < M)
                    vh = *reinterpret_cast<const uint4*>(A + (size_t)row * K + k0 + c8 * 8);
                rha[i] = vh;
            }
        }
        #pragma unroll
        for (int i = 0; i < NB; i++) {
            int slot = tid + i * THREADS;
            int r = slot / (BK / 8);
            int c8 = slot % (BK / 8);
            rhb[i] = *reinterpret_cast<const uint4*>(B + (size_t)(col0 + r) * K + k0 + c8 * 8);
        }
    };

    auto STORE = [&]() {
        #pragma unroll
        for (int i = 0; i < NA; i++) {
            int slot = tid + i * THREADS;
            int r = slot / (BK / 8);
            int c8 = slot % (BK / 8);
            if (CONV_A) {
                __half h[8];
                #pragma unroll
                for (int q = 0; q < 8; q++) h[q] = __float2half_rn(rfa[i][q]);
                *reinterpret_cast<uint4*>(&Ah[r][c8 * 8]) =
                    make_uint4(pack_h2(h[0],h[1]), pack_h2(h[2],h[3]),
                               pack_h2(h[4],h[5]), pack_h2(h[6],h[7]));
            } else {
                *reinterpret_cast<uint4*>(&Ah[r][c8 * 8]) = rha[i];
            }
        }
        #pragma unroll
        for (int i = 0; i < NB; i++) {
            int slot = tid + i * THREADS;
            int r = slot / (BK / 8);
            int c8 = slot % (BK / 8);
            *reinterpret_cast<uint4*>(&Bhs[r][c8 * 8]) = rhb[i];
        }
    };

    LOAD(0);
    STORE();
    __syncthreads();

    for (int t = 0; t < T; t++) {
        if (t + 1 < T) LOAD((t + 1) * BK);

        #pragma unroll
        for (int ks = 0; ks < BK; ks += 16) {
            unsigned ah[MT][4], bh[NT][2];
            #pragma unroll
            for (int mt = 0; mt < MT; mt++) {
                int r = wm * WTM + mt * 16 + (lane & 15);
                int c = ks + ((lane >> 4) << 3);
                ldsm_x4(ah[mt][0], ah[mt][1], ah[mt][2], ah[mt][3],
                        sAh + (unsigned)((r * LDS_ + c) * 2));
            }
            #pragma unroll
            for (int nt = 0; nt < NT; nt++) {
                int r = wn * WTN + nt * 8 + (lane & 7);
                int c = ks + (((lane >> 3) & 1) << 3);
                ldsm_x2(bh[nt][0], bh[nt][1], sBh + (unsigned)((r * LDS_ + c) * 2));
            }
            #pragma unroll
            for (int mt = 0; mt < MT; mt++)
                #pragma unroll
                for (int nt = 0; nt < NT; nt++)
                    mma16816(acc[mt][nt], ah[mt], bh[nt]);
        }
        __syncthreads();
        if (t + 1 < T) {
            STORE();
            __syncthreads();
        }
    }

    __half* Ch = devbufh(hsel ? c1h_id : c0h_id);
    #pragma unroll
    for (int mt = 0; mt < MT; mt++) {
        #pragma unroll
        for (int nt = 0; nt < NT; nt++) {
            int r0 = row0 + wm * WTM + mt * 16 + g;
            int c = col0 + wn * WTN + nt * 8 + tig * 2;
            if (r0 < M)
                *reinterpret_cast<unsigned*>(&Ch[(size_t)r0 * Nh + c]) =
                    pack_h2(__float2half_rn(acc[mt][nt][0]), __float2half_rn(acc[mt][nt][1]));
            if (r0 + 8 < M)
                *reinterpret_cast<unsigned*>(&Ch[(size_t)(r0 + 8) * Nh + c]) =
                    pack_h2(__float2half_rn(acc[mt][nt][2]), __float2half_rn(acc[mt][nt][3]));
        }
    }
}

// ---------------- GATv2 layer 1 aggregation (half2 score math, node-range) ----------------
__device__ __forceinline__ float score_h2(const uint4& u, const __half2* xr2,
                                          const __half2* att2, const __half2 neg2) {
    const __half2* vh = reinterpret_cast<const __half2*>(&u);
    __half2 p2 = __float2half2_rn(0.f);
    #pragma unroll
    for (int j = 0; j < 4; j++) {
        __half2 t = __hadd2(vh[j], xr2[j]);
        t = __hmax2(t, __hmul2(neg2, t));
        p2 = __hfma2(t, att2[j], p2);
    }
    float2 pf = __half22float2(p2);
    float p = pf.x + pf.y;
    p += __shfl_xor_sync(FULLMASK, p, 1);
    p += __shfl_xor_sync(FULLMASK, p, 2);
    return fminf(p, 80.f);
}
__device__ __forceinline__ void acc_h2(float* acc, const uint4& u, float f) {
    const __half2* vh = reinterpret_cast<const __half2*>(&u);
    #pragma unroll
    for (int j = 0; j < 4; j++) {
        float2 fv = __half22float2(vh[j]);
        acc[2 * j]     = fmaf(f, fv.x, acc[2 * j]);
        acc[2 * j + 1] = fmaf(f, fv.y, acc[2 * j + 1]);
    }
}

__global__ __launch_bounds__(256)
void gat1_agg_kernel(const float* __restrict__ att1, const float* __restrict__ b1,
                     int nodeBase, int nNodes) {
    const int wid = threadIdx.x >> 5;
    const int lane = threadIdx.x & 31;
    const int node = nodeBase + blockIdx.x * (blockDim.x >> 5) + wid;
    if (node >= nodeBase + nNodes || node >= N_NODES) return;

    __half2 att2[4], xr2[4];
    #pragma unroll
    for (int j = 0; j < 4; j++)
        att2[j] = __floats2half2_rn(__ldg(att1 + lane * 8 + 2 * j),
                                    __ldg(att1 + lane * 8 + 2 * j + 1));
    {
        uint4 uxr = *reinterpret_cast<const uint4*>(g_xr1h + (size_t)node * C1 + lane * 8);
        const __half2* p = reinterpret_cast<const __half2*>(&uxr);
        #pragma unroll
        for (int j = 0; j < 4; j++) xr2[j] = p[j];
    }
    const __half2 neg2 = __float2half2_rn(NEG);

    float d, acc[8];
    #pragma unroll
    for (int j = 0; j < 8; j++) acc[j] = 0.f;
    {   // self loop
        uint4 u = *reinterpret_cast<const uint4*>(g_xl1h + (size_t)node * C1 + lane * 8);
        float f = __expf(score_h2(u, xr2, att2, neg2));
        d = f;
        acc_h2(acc, u, f);
    }

    const int cnt_all = min(g_cnt[node], MAXDEG);
    const int* adj = g_adj + (size_t)node * MAXDEG;
    for (int base = 0; base < cnt_all; base += 32) {
        int sv = 0;
        if (base + lane < cnt_all) sv = adj[base + lane];
        const int cnt = min(32, cnt_all - base);
        int t = 0;
        for (; t + 3 < cnt; t += 4) {
            int sa = __shfl_sync(FULLMASK, sv, t);
            int sb = __shfl_sync(FULLMASK, sv, t + 1);
            int sc = __shfl_sync(FULLMASK, sv, t + 2);
            int sd = __shfl_sync(FULLMASK, sv, t + 3);
            uint4 ua = *reinterpret_cast<const uint4*>(g_xl1h + (size_t)sa * C1 + lane * 8);
            uint4 ub = *reinterpret_cast<const uint4*>(g_xl1h + (size_t)sb * C1 + lane * 8);
            uint4 uc = *reinterpret_cast<const uint4*>(g_xl1h + (size_t)sc * C1 + lane * 8);
            uint4 ud = *reinterpret_cast<const uint4*>(g_xl1h + (size_t)sd * C1 + lane * 8);
            float fa = __expf(score_h2(ua, xr2, att2, neg2));
            float fb = __expf(score_h2(ub, xr2, att2, neg2));
            float fc = __expf(score_h2(uc, xr2, att2, neg2));
            float fd = __expf(score_h2(ud, xr2, att2, neg2));
            d += (fa + fb) + (fc + fd);
            acc_h2(acc, ua, fa);
            acc_h2(acc, ub, fb);
            acc_h2(acc, uc, fc);
            acc_h2(acc, ud, fd);
        }
        for (; t < cnt; t++) {
            int sa = __shfl_sync(FULLMASK, sv, t);
            uint4 ua = *reinterpret_cast<const uint4*>(g_xl1h + (size_t)sa * C1 + lane * 8);
            float fa = __expf(score_h2(ua, xr2, att2, neg2));
            d += fa;
            acc_h2(acc, ua, fa);
        }
    }

    const float inv = 1.f / d;
    __half h[8];
    #pragma unroll
    for (int j = 0; j < 8; j++) {
        float hv = fmaf(acc[j], inv, __ldg(b1 + lane * 8 + j));
        hv = (hv > 0.f) ? hv : expm1f(hv);
        h[j] = __float2half_rn(hv);
    }
    *reinterpret_cast<uint4*>(g_h1h + (size_t)node * C1 + lane * 8) =
        make_uint4(pack_h2(h[0],h[1]), pack_h2(h[2],h[3]),
                   pack_h2(h[4],h[5]), pack_h2(h[6],h[7]));
}

// ---------------- preout ----------------
__global__ __launch_bounds__(256)
void preout_kernel(const float* __restrict__ x, const float* __restrict__ Wc,
                   const float* __restrict__ bc, float* __restrict__ out) {
    __shared__ float Wt[40][129];
    __shared__ float bcs[40];
    __shared__ float xs[8][128];

    const int tid = threadIdx.x;
    for (int idx = tid; idx < 128 * 40; idx += 256) {
        int k = idx / 40, o = idx % 40;
        Wt[o][k] = Wc[(32 + k) * 40 + o];
    }
    if (tid < 40) bcs[tid] = bc[tid];
    __syncthreads();

    const int wid = tid >> 5;
    const int lane = tid & 31;
    const int node = blockIdx.x * 8 + wid;
    if (node >= N_NODES) return;

    reinterpret_cast<float4*>(xs[wid])[lane] =
        reinterpret_cast<const float4*>(x + (size_t)node * 128)[lane];
    __syncwarp();

    float a0 = bcs[lane];
    float a1 = (lane < 8) ? bcs[32 + lane] : 0.f;
    #pragma unroll 4
    for (int k = 0; k < 128; k++) {
        float xv = xs[wid][k];
        a0 = fmaf(xv, Wt[lane][k], a0);
        if (lane < 8) a1 = fmaf(xv, Wt[32 + lane][k], a1);
    }
    out[(size_t)node * 40 + lane] = a0;
    if (lane < 8) out[(size_t)node * 40 + 32 + lane] = a1;
}

// ---------------- GATv2 layer 2 (half2-packed shuffles, 2 edges/reduction) ----------------
__global__ __launch_bounds__(256)
void gat2_final_kernel(const float* __restrict__ att2p, const float* __restrict__ b2,
                       const float* __restrict__ Wc, float* __restrict__ out) {
    __shared__ float Wct[32 * 40];
    __shared__ float h2s[8][33];

    const int tid = threadIdx.x;
    for (int idx = tid; idx < 32 * 40; idx += blockDim.x) Wct[idx] = Wc[idx];
    __syncthreads();

    const int wid = tid >> 5;
    const int lane = tid & 31;
    const int node = blockIdx.x * (blockDim.x >> 5) + wid;
    if (node >= N_NODES) return;

    const float attf = __ldg(att2p + lane);
    const __half2 atth2 = __float2half2_rn(attf);
    const __half xrh = g_xr2h[(size_t)node * C2 + lane];
    const __half2 xrh2 = __half2half2(xrh);
    const float xr = __half2float(xrh);
    const __half2 neg2 = __float2half2_rn(NEG);

    float d, acc;
    {   // self loop (fp32 path, once)
        float v = __half2float(g_xl2h[(size_t)node * C2 + lane]);
        float t = v + xr;
        t = fmaxf(t, NEG * t);
        float p = t * attf;
        #pragma unroll
        for (int o = 16; o; o >>= 1) p += __shfl_xor_sync(FULLMASK, p, o);
        float f = __expf(fminf(p, 80.f));
        d = f; acc = f * v;
    }

    const int cnt_all = min(g_cnt[node], MAXDEG);
    const int* adj = g_adj + (size_t)node * MAXDEG;
    for (int base = 0; base < cnt_all; base += 32) {
        int sv = 0;
        if (base + lane < cnt_all) sv = adj[base + lane];
        const int cnt = min(32, cnt_all - base);
        int t = 0;
        for (; t + 3 < cnt; t += 4) {
            int sa = __shfl_sync(FULLMASK, sv, t);
            int sb = __shfl_sync(FULLMASK, sv, t + 1);
            int sc = __shfl_sync(FULLMASK, sv, t + 2);
            int sd = __shfl_sync(FULLMASK, sv, t + 3);
            __half ha = __ldg(g_xl2h + (size_t)sa * C2 + lane);
            __half hb = __ldg(g_xl2h + (size_t)sb * C2 + lane);
            __half hc = __ldg(g_xl2h + (size_t)sc * C2 + lane);
            __half hd = __ldg(g_xl2h + (size_t)sd * C2 + lane);
            // packed score math: 2 edges per half2
            __half2 vab = __halves2half2(ha, hb);
            __half2 vcd = __halves2half2(hc, hd);
            __half2 tab = __hadd2(vab, xrh2);
            __half2 tcd = __hadd2(vcd, xrh2);
            tab = __hmax2(tab, __hmul2(neg2, tab));
            tcd = __hmax2(tcd, __hmul2(neg2, tcd));
            __half2 pab = __hmul2(tab, atth2);
            __half2 pcd = __hmul2(tcd, atth2);
            #pragma unroll
            for (int o = 16; o; o >>= 1) {
                pab = __hadd2(pab, shfl_xor_h2(pab, o));
                pcd = __hadd2(pcd, shfl_xor_h2(pcd, o));
            }
            float2 sab = __half22float2(pab);
            float2 scd = __half22float2(pcd);
            float fa = __expf(fminf(sab.x, 80.f));
            float fb = __expf(fminf(sab.y, 80.f));
            float fc = __expf(fminf(scd.x, 80.f));
            float fd = __expf(fminf(scd.y, 80.f));
            d += (fa + fb) + (fc + fd);
            float2 fvab = __half22float2(vab);
            float2 fvcd = __half22float2(vcd);
            acc = fmaf(fd, fvcd.y, fmaf(fc, fvcd.x, fmaf(fb, fvab.y, fmaf(fa, fvab.x, acc))));
        }
        for (; t < cnt; t++) {
            int sa = __shfl_sync(FULLMASK, sv, t);
            float va = __half2float(__ldg(g_xl2h + (size_t)sa * C2 + lane));
            float ta = va + xr; ta = fmaxf(ta, NEG * ta);
            float pa = ta * attf;
            #pragma unroll
            for (int o = 16; o; o >>= 1) pa += __shfl_xor_sync(FULLMASK, pa, o);
            float fa = __expf(fminf(pa, 80.f));
            d += fa;
            acc = fmaf(fa, va, acc);
        }
    }

    float h2 = fmaf(acc, 1.f / d, __ldg(b2 + lane));
    h2 = (h2 > 0.f) ? h2 : expm1f(h2);
    h2s[wid][lane] = h2;
    __syncwarp();

    float a0 = 0.f, a1 = 0.f;
    #pragma unroll 4
    for (int k = 0; k < 32; k++) {
        float hv = h2s[wid][k];
        a0 = fmaf(hv, Wct[k * 40 + lane], a0);
        if (lane < 8) a1 = fmaf(hv, Wct[k * 40 + 32 + lane], a1);
    }
    out[(size_t)node * 40 + lane] += a0;
    if (lane < 8) out[(size_t)node * 40 + 32 + lane] += a1;
}

// ---------------- launch ----------------
extern "C" void kernel_launch(void* const* d_in, const int* in_sizes, int n_in,
                              void* d_out, int out_size) {
    const float* x    = (const float*)d_in[0];
    const void*  ei   = (const void*)d_in[1];
    const float* W1l  = (const float*)d_in[2];
    const float* W1r  = (const float*)d_in[3];
    const float* att1 = (const float*)d_in[4];
    const float* b1   = (const float*)d_in[5];
    const float* W2l  = (const float*)d_in[6];
    const float* W2r  = (const float*)d_in[7];
    const float* att2 = (const float*)d_in[8];
    const float* b2   = (const float*)d_in[9];
    const float* Wc   = (const float*)d_in[10];
    const float* bc   = (const float*)d_in[11];
    float* out = (float*)d_out;

    static cudaStream_t sB = nullptr, sC = nullptr;
    static cudaEvent_t eF = nullptr, eB = nullptr, eW = nullptr, eW2 = nullptr,
                       eA = nullptr, eG2A = nullptr;
    if (sB == nullptr) {
        cudaStreamCreateWithFlags(&sB, cudaStreamNonBlocking);
        cudaStreamCreateWithFlags(&sC, cudaStreamNonBlocking);
        cudaEventCreateWithFlags(&eF, cudaEventDisableTiming);
        cudaEventCreateWithFlags(&eB, cudaEventDisableTiming);
        cudaEventCreateWithFlags(&eW, cudaEventDisableTiming);
        cudaEventCreateWithFlags(&eW2, cudaEventDisableTiming);
        cudaEventCreateWithFlags(&eA, cudaEventDisableTiming);
        cudaEventCreateWithFlags(&eG2A, cudaEventDisableTiming);
    }

    cudaEventRecord(eF, 0);
    cudaStreamWaitEvent(sB, eF, 0);
    cudaStreamWaitEvent(sC, eF, 0);

    init_kernel<<<(N_NODES + 255) / 256, 256, 0, sB>>>(ei);                          // 1
    conv_w_kernel<<<(C1 * 128 + 255) / 256, 256, 0, sC>>>(W1l, BUFH_B1L, 128, C1);   // 2
    conv_w_kernel<<<(C1 * 128 + 255) / 256, 256, 0, sC>>>(W1r, BUFH_B1R, 128, C1);   // 3
    cudaEventRecord(eW, sC);

    cudaStreamWaitEvent(0, eW, 0);
    {
        dim3 grid((N_NODES + 127) / 128, (2 * C1) / 128);
        hgemm_dual_kernel<128, 128, 32, 2, 4, 128, true><<<grid, 256>>>(             // 4 (profiled)
            x, -1, BUFH_B1L, BUFH_B1R, BUFH_XL1H, BUFH_XR1H, N_NODES, C1, 0);
    }

    scatter_direct_kernel<<<(N_EDGES + 255) / 256, 256, 0, sB>>>(ei);
    cudaEventRecord(eB, sB);

    conv_w_kernel<<<(C2 * 256 + 255) / 256, 256, 0, sC>>>(W2l, BUFH_B2L, 256, C2);
    conv_w_kernel<<<(C2 * 256 + 255) / 256, 256, 0, sC>>>(W2r, BUFH_B2R, 256, C2);
    cudaEventRecord(eW2, sC);
    preout_kernel<<<(N_NODES + 7) / 8, 256, 0, sC>>>(x, Wc, bc, out);

    // gat1 split: half A then half B on main stream
    cudaStreamWaitEvent(0, eB, 0);
    gat1_agg_kernel<<<NHALF / 8, 256>>>(att1, b1, 0, NHALF);
    cudaEventRecord(eA, 0);
    gat1_agg_kernel<<<(N_NODES - NHALF + 7) / 8, 256>>>(att1, b1, NHALF, N_NODES - NHALF);

    // GEMM2 half A on sC (overlaps gat1 half B); needs w2 (sC in-order) + gat1A
    cudaStreamWaitEvent(sC, eA, 0);
    {
        dim3 grid(NHALF / 128, (2 * C2) / 32);
        hgemm_dual_kernel<128, 32, 64, 4, 1, 256, false><<<grid, 128, 0, sC>>>(
            nullptr, BUFH_H1H, BUFH_B2L, BUFH_B2R, BUFH_XL2H, BUFH_XR2H, N_NODES, C2, 0);
    }
    cudaEventRecord(eG2A, sC);

    // GEMM2 half B on main (after gat1B in-order; needs w2 weights)
    cudaStreamWaitEvent(0, eW2, 0);
    {
        dim3 grid((N_NODES - NHALF + 127) / 128, (2 * C2) / 32);
        hgemm_dual_kernel<128, 32, 64, 4, 1, 256, false><<<grid, 128>>>(
            nullptr, BUFH_H1H, BUFH_B2L, BUFH_B2R, BUFH_XL2H, BUFH_XR2H, N_NODES, C2, NHALF);
    }

    cudaStreamWaitEvent(0, eG2A, 0);   // implies preout done (sC in-order)
    gat2_final_kernel<<<(N_NODES + 7) / 8, 256>>>(att2, b2, Wc, out);
}